// round 14
// baseline (speedup 1.0000x reference)
#include <cuda_runtime.h>
#include <cuda_fp16.h>
#include <math.h>
#include <stdint.h>

#define NMAX 100096
#define EMAX 3200000
#define HDIM 128
#define NGRAPH 64
#define NBLK 128   // max scan blocks (ceil(NMAX/1024))

// ---------------- scratch (static __device__, no allocation) ----------------
__device__ __half g_u[(size_t)NMAX * HDIM];  // u = x @ W (fp16, unscaled)
__device__ __half g_h[(size_t)NMAX * HDIM];  // layer output (fp16)
__device__ float  g_dinv[NMAX];
__device__ int    g_counts[NMAX];
__device__ int    g_cursor[NMAX];
__device__ int    g_rowptr[NMAX + 1];
__device__ int    g_esrc[EMAX];
__device__ float  g_pool[NGRAPH * HDIM];
__device__ int    g_bsum[NBLK];
__device__ int    g_boff[NBLK];

// ---------------- helpers ----------------
__device__ __forceinline__ void mma_fp16(float* c, const uint32_t* a, const uint32_t* b) {
    asm("mma.sync.aligned.m16n8k16.row.col.f32.f16.f16.f32 "
        "{%0,%1,%2,%3}, {%4,%5,%6,%7}, {%8,%9}, {%0,%1,%2,%3};"
        : "+f"(c[0]), "+f"(c[1]), "+f"(c[2]), "+f"(c[3])
        : "r"(a[0]), "r"(a[1]), "r"(a[2]), "r"(a[3]), "r"(b[0]), "r"(b[1]));
}
// load 8 consecutive A elems -> 4 half2 regs (fp32 / fp16 source overloads)
__device__ __forceinline__ void loadA8(const float* p, uint32_t* d) {
    float4 a = __ldcs((const float4*)p);
    float4 b = __ldcs((const float4*)(p + 4));
    __half2 h0 = __floats2half2_rn(a.x, a.y);
    __half2 h1 = __floats2half2_rn(a.z, a.w);
    __half2 h2 = __floats2half2_rn(b.x, b.y);
    __half2 h3 = __floats2half2_rn(b.z, b.w);
    d[0] = *(uint32_t*)&h0; d[1] = *(uint32_t*)&h1;
    d[2] = *(uint32_t*)&h2; d[3] = *(uint32_t*)&h3;
}
__device__ __forceinline__ void loadA8(const __half* p, uint32_t* d) {
    uint4 v = __ldcs((const uint4*)p);
    d[0] = v.x; d[1] = v.y; d[2] = v.z; d[3] = v.w;
}

// ---------------- zero scratch ----------------
__global__ void zero_kernel(int n) {
    int i = blockIdx.x * blockDim.x + threadIdx.x;
    if (i < n) g_counts[i] = 0;
    if (i < NGRAPH * HDIM) g_pool[i] = 0.0f;
}

// ---------------- in-degree histogram over dst ----------------
__global__ void hist_kernel(const int* __restrict__ dst, int E) {
    int e = blockIdx.x * blockDim.x + threadIdx.x;
    if (e < E) atomicAdd(&g_counts[__ldcs(dst + e)], 1);
}

// ---------------- scan phase 1: per-block (1024 elems) sums, coalesced ------
__global__ void scan1_kernel(int n) {
    int b = blockIdx.x, t = threadIdx.x;
    int base = b * 1024 + t * 4;
    int s = 0;
    if (base + 3 < n) {
        int4 c = *(const int4*)&g_counts[base];
        s = c.x + c.y + c.z + c.w;
    } else {
        for (int j = 0; j < 4; j++) if (base + j < n) s += g_counts[base + j];
    }
#pragma unroll
    for (int d = 16; d > 0; d >>= 1) s += __shfl_down_sync(0xffffffffu, s, d);
    __shared__ int ws[8];
    if ((t & 31) == 0) ws[t >> 5] = s;
    __syncthreads();
    if (t == 0) {
        int tot = 0;
#pragma unroll
        for (int w = 0; w < 8; w++) tot += ws[w];
        g_bsum[b] = tot;
    }
}

// ---------------- scan phase 2: scan block sums (nb <= 128) -----------------
__global__ void scan2_kernel(int nb, int n) {
    int t = threadIdx.x;  // 128 threads
    int v = (t < nb) ? g_bsum[t] : 0;
    int incl = v;
#pragma unroll
    for (int d = 1; d < 32; d <<= 1) {
        int o = __shfl_up_sync(0xffffffffu, incl, d);
        if ((t & 31) >= d) incl += o;
    }
    __shared__ int ws[4];
    if ((t & 31) == 31) ws[t >> 5] = incl;
    __syncthreads();
    int woff = 0;
#pragma unroll
    for (int w = 0; w < 4; w++) if (w < (t >> 5)) woff += ws[w];
    incl += woff;
    if (t < nb) g_boff[t] = incl - v;   // exclusive
    if (t == 127) g_rowptr[n] = incl;   // total
}

// ---------------- scan phase 3: local prefix + offset; rowptr/cursor/dinv ---
__global__ void scan3_kernel(int n) {
    int b = blockIdx.x, t = threadIdx.x;
    int base = b * 1024 + t * 4;
    int4 c = make_int4(0, 0, 0, 0);
    if (base + 3 < n) {
        c = *(const int4*)&g_counts[base];
    } else {
        if (base + 0 < n) c.x = g_counts[base + 0];
        if (base + 1 < n) c.y = g_counts[base + 1];
        if (base + 2 < n) c.z = g_counts[base + 2];
        if (base + 3 < n) c.w = g_counts[base + 3];
    }
    int s = c.x + c.y + c.z + c.w;
    int incl = s;
#pragma unroll
    for (int d = 1; d < 32; d <<= 1) {
        int o = __shfl_up_sync(0xffffffffu, incl, d);
        if ((t & 31) >= d) incl += o;
    }
    __shared__ int ws[8];
    if ((t & 31) == 31) ws[t >> 5] = incl;
    __syncthreads();
    int woff = 0;
#pragma unroll
    for (int w = 0; w < 8; w++) if (w < (t >> 5)) woff += ws[w];
    int run = g_boff[b] + woff + incl - s;
    if (base + 0 < n) { g_rowptr[base+0]=run; g_cursor[base+0]=run; g_dinv[base+0]=rsqrtf((float)c.x+1.f); run+=c.x; }
    if (base + 1 < n) { g_rowptr[base+1]=run; g_cursor[base+1]=run; g_dinv[base+1]=rsqrtf((float)c.y+1.f); run+=c.y; }
    if (base + 2 < n) { g_rowptr[base+2]=run; g_cursor[base+2]=run; g_dinv[base+2]=rsqrtf((float)c.z+1.f); run+=c.z; }
    if (base + 3 < n) { g_rowptr[base+3]=run; g_cursor[base+3]=run; g_dinv[base+3]=rsqrtf((float)c.w+1.f); }
}

// ---------------- fill CSR with src ids (cursor pre-seeded to rowptr) -------
__global__ void fill_kernel(const int* __restrict__ src,
                            const int* __restrict__ dst, int E) {
    int e = blockIdx.x * blockDim.x + threadIdx.x;
    if (e < E) {
        int d = __ldcs(dst + e);
        int pos = atomicAdd(&g_cursor[d], 1);
        g_esrc[pos] = __ldcs(src + e);
    }
}

// ---------------- fp16 tensor-core GEMM (m16n8k16, fp32 accum) --------------
template<typename T>
__global__ __launch_bounds__(256, 2) void sgemm_fp16(
    const T* __restrict__ A, const float* __restrict__ B,
    __half* __restrict__ U, int N, int K)
{
    __shared__ uint32_t As2[2][128][12];   // [row][k/2] half2
    __shared__ uint32_t Bs2[2][128][12];   // [col][k/2] half2 (transposed)

    int tid = threadIdx.x;
    int wid = tid >> 5, lane = tid & 31;
    int g = lane >> 2, t = lane & 3;
    int warp_m = wid >> 2, warp_n = wid & 3;
    int row0 = blockIdx.x * 128;
    int m0 = warp_m * 64, n0 = warp_n * 32;

    float acc[4][4][4];
#pragma unroll
    for (int mi = 0; mi < 4; mi++)
#pragma unroll
        for (int ni = 0; ni < 4; ni++)
#pragma unroll
            for (int r = 0; r < 4; r++) acc[mi][ni][r] = 0.0f;

    int a_r = tid >> 1;
    int a_h = (tid & 1) * 4;
    int garow = row0 + a_r;
    const T* Arow = A + (size_t)(garow < N ? garow : 0) * K + a_h * 2;

    int b_cg = lane >> 2;   // 0..7
    int b_k2 = lane & 3;    // 0..3

    uint32_t areg[4], breg[4];

    loadA8(Arow, areg);
#pragma unroll
    for (int p = 0; p < 4; p++) {
        int c  = wid * 16 + (p & 1) * 8 + b_cg;
        int k2 = b_k2 + (p >> 1) * 4;
        float lo = __ldg(&B[(size_t)(2 * k2) * HDIM + c]);
        float hi = __ldg(&B[(size_t)(2 * k2 + 1) * HDIM + c]);
        __half2 hh = __floats2half2_rn(lo, hi);
        breg[p] = *(uint32_t*)&hh;
    }
#pragma unroll
    for (int j = 0; j < 4; j++) As2[0][a_r][a_h + j] = areg[j];
#pragma unroll
    for (int p = 0; p < 4; p++) {
        int c  = wid * 16 + (p & 1) * 8 + b_cg;
        int k2 = b_k2 + (p >> 1) * 4;
        Bs2[0][c][k2] = breg[p];
    }
    __syncthreads();

    int buf = 0;
    for (int k0 = 0; k0 < K; k0 += 16) {
        int nk = k0 + 16;
        if (nk < K) {
            loadA8(Arow + nk, areg);
#pragma unroll
            for (int p = 0; p < 4; p++) {
                int c  = wid * 16 + (p & 1) * 8 + b_cg;
                int k2 = b_k2 + (p >> 1) * 4;
                float lo = __ldg(&B[(size_t)(nk + 2 * k2) * HDIM + c]);
                float hi = __ldg(&B[(size_t)(nk + 2 * k2 + 1) * HDIM + c]);
                __half2 hh = __floats2half2_rn(lo, hi);
                breg[p] = *(uint32_t*)&hh;
            }
        }
        uint32_t bf[4][2];
#pragma unroll
        for (int ni = 0; ni < 4; ni++) {
            int col = n0 + ni * 8 + g;
            bf[ni][0] = Bs2[buf][col][t];
            bf[ni][1] = Bs2[buf][col][t + 4];
        }
#pragma unroll
        for (int mi = 0; mi < 4; mi++) {
            int r1 = m0 + mi * 16 + g;
            uint32_t af[4];
            af[0] = As2[buf][r1][t];
            af[1] = As2[buf][r1 + 8][t];
            af[2] = As2[buf][r1][t + 4];
            af[3] = As2[buf][r1 + 8][t + 4];
#pragma unroll
            for (int ni = 0; ni < 4; ni++)
                mma_fp16(acc[mi][ni], af, bf[ni]);
        }
        if (nk < K) {
            int nb = buf ^ 1;
#pragma unroll
            for (int j = 0; j < 4; j++) As2[nb][a_r][a_h + j] = areg[j];
#pragma unroll
            for (int p = 0; p < 4; p++) {
                int c  = wid * 16 + (p & 1) * 8 + b_cg;
                int k2 = b_k2 + (p >> 1) * 4;
                Bs2[nb][c][k2] = breg[p];
            }
        }
        __syncthreads();
        buf ^= 1;
    }

#pragma unroll
    for (int mi = 0; mi < 4; mi++) {
        int r1 = row0 + m0 + mi * 16 + g;
        int r2 = r1 + 8;
#pragma unroll
        for (int ni = 0; ni < 4; ni++) {
            int c = n0 + ni * 8 + 2 * t;
            if (r1 < N) {
                __half2 h = __floats2half2_rn(acc[mi][ni][0], acc[mi][ni][1]);
                __stcs((__half2*)&U[(size_t)r1 * HDIM + c], h);
            }
            if (r2 < N) {
                __half2 h = __floats2half2_rn(acc[mi][ni][2], acc[mi][ni][3]);
                __stcs((__half2*)&U[(size_t)r2 * HDIM + c], h);
            }
        }
    }
}

// ---------------- CSR gather aggregation: 2 warps per dst row ---------------
// Warp handles 64 features (one 128B line per gathered row).
// Out[v] = half( relu( dinv[v]*( sum_{in} dinv[s]*U[s] + dinv[v]*U[v] ) + b ) )
__global__ __launch_bounds__(256) void agg_kernel(
    const __half* __restrict__ Uin, __half* __restrict__ Out,
    const float* __restrict__ bias, int N)
{
    int gwarp = (blockIdx.x * blockDim.x + threadIdx.x) >> 5;
    int lane = threadIdx.x & 31;
    int v = gwarp >> 1;
    if (v >= N) return;
    int half = gwarp & 1;
    int co = half * 64 + lane * 2;          // fp16 column offset (2 per lane)
    const __half* Ucol = Uin + co;

    int beg = g_rowptr[v], end = g_rowptr[v + 1];
    float dv = g_dinv[v];

    // self loop
    uint32_t sw = *(const uint32_t*)&Ucol[(size_t)v * HDIM];
    float2 f = __half22float2(*(__half2*)&sw);
    float2 acc0 = make_float2(dv * f.x, dv * f.y);
    float2 acc1 = make_float2(0.f, 0.f);
    float2 acc2 = make_float2(0.f, 0.f);
    float2 acc3 = make_float2(0.f, 0.f);

    for (int base = beg; base < end; base += 32) {
        int nn = min(32, end - base);
        int sl = 0; float dvl = 0.f;
        if (lane < nn) { sl = __ldcs(&g_esrc[base + lane]); dvl = g_dinv[sl]; }
        int j = 0;
        for (; j + 3 < nn; j += 4) {
            int s0 = __shfl_sync(0xffffffffu, sl, j);
            int s1 = __shfl_sync(0xffffffffu, sl, j + 1);
            int s2 = __shfl_sync(0xffffffffu, sl, j + 2);
            int s3 = __shfl_sync(0xffffffffu, sl, j + 3);
            float d0 = __shfl_sync(0xffffffffu, dvl, j);
            float d1 = __shfl_sync(0xffffffffu, dvl, j + 1);
            float d2 = __shfl_sync(0xffffffffu, dvl, j + 2);
            float d3 = __shfl_sync(0xffffffffu, dvl, j + 3);
            uint32_t w0 = *(const uint32_t*)&Ucol[(size_t)s0 * HDIM];
            uint32_t w1 = *(const uint32_t*)&Ucol[(size_t)s1 * HDIM];
            uint32_t w2 = *(const uint32_t*)&Ucol[(size_t)s2 * HDIM];
            uint32_t w3 = *(const uint32_t*)&Ucol[(size_t)s3 * HDIM];
            float2 a = __half22float2(*(__half2*)&w0);
            float2 b = __half22float2(*(__half2*)&w1);
            float2 c = __half22float2(*(__half2*)&w2);
            float2 e = __half22float2(*(__half2*)&w3);
            acc0.x = fmaf(d0, a.x, acc0.x); acc0.y = fmaf(d0, a.y, acc0.y);
            acc1.x = fmaf(d1, b.x, acc1.x); acc1.y = fmaf(d1, b.y, acc1.y);
            acc2.x = fmaf(d2, c.x, acc2.x); acc2.y = fmaf(d2, c.y, acc2.y);
            acc3.x = fmaf(d3, e.x, acc3.x); acc3.y = fmaf(d3, e.y, acc3.y);
        }
        for (; j < nn; j++) {
            int s0 = __shfl_sync(0xffffffffu, sl, j);
            float d0 = __shfl_sync(0xffffffffu, dvl, j);
            uint32_t w0 = *(const uint32_t*)&Ucol[(size_t)s0 * HDIM];
            float2 a = __half22float2(*(__half2*)&w0);
            acc0.x = fmaf(d0, a.x, acc0.x); acc0.y = fmaf(d0, a.y, acc0.y);
        }
    }
    float ax = acc0.x + acc1.x + acc2.x + acc3.x;
    float ay = acc0.y + acc1.y + acc2.y + acc3.y;
    float2 bb = *(const float2*)&bias[co];
    float ox = fmaxf(fmaf(dv, ax, bb.x), 0.f);
    float oy = fmaxf(fmaf(dv, ay, bb.y), 0.f);
    __half2 h = __floats2half2_rn(ox, oy);
    __stcs((__half2*)&Out[(size_t)v * HDIM + co], h);
}

// ---------------- global max pool per graph (fp16 in, batch sorted) ---------
__global__ void pool_kernel(const __half* __restrict__ Hin,
                            const int* __restrict__ batch, int N)
{
    const int NPW = 16;
    int gwarp = (blockIdx.x * blockDim.x + threadIdx.x) >> 5;
    int lane = threadIdx.x & 31;
    int v0 = gwarp * NPW;
    if (v0 >= N) return;
    int vend = min(v0 + NPW, N);

    int cur_b = batch[v0];
    uint2 w = __ldcs((const uint2*)&Hin[(size_t)v0 * HDIM + lane * 4]);
    float2 m0 = __half22float2(*(__half2*)&w.x);
    float2 m1 = __half22float2(*(__half2*)&w.y);
    float4 m = make_float4(m0.x, m0.y, m1.x, m1.y);
    for (int v = v0 + 1; v < vend; v++) {
        int b = batch[v];
        w = __ldcs((const uint2*)&Hin[(size_t)v * HDIM + lane * 4]);
        float2 x0 = __half22float2(*(__half2*)&w.x);
        float2 x1 = __half22float2(*(__half2*)&w.y);
        float4 x = make_float4(x0.x, x0.y, x1.x, x1.y);
        if (b != cur_b) {
            int* p = (int*)&g_pool[cur_b * HDIM + lane * 4];
            atomicMax(p + 0, __float_as_int(m.x));
            atomicMax(p + 1, __float_as_int(m.y));
            atomicMax(p + 2, __float_as_int(m.z));
            atomicMax(p + 3, __float_as_int(m.w));
            m = x; cur_b = b;
        } else {
            m.x = fmaxf(m.x, x.x); m.y = fmaxf(m.y, x.y);
            m.z = fmaxf(m.z, x.z); m.w = fmaxf(m.w, x.w);
        }
    }
    int* p = (int*)&g_pool[cur_b * HDIM + lane * 4];
    atomicMax(p + 0, __float_as_int(m.x));
    atomicMax(p + 1, __float_as_int(m.y));
    atomicMax(p + 2, __float_as_int(m.z));
    atomicMax(p + 3, __float_as_int(m.w));
}

// ---------------- classifier head + log_softmax -----------------------------
__global__ void head_kernel(const float* __restrict__ Wc,
                            const float* __restrict__ bc,
                            float* __restrict__ out)
{
    int gi = threadIdx.x;  // 64 graphs
    float z0 = bc[0], z1 = bc[1];
#pragma unroll 8
    for (int k = 0; k < HDIM; k++) {
        float v = g_pool[gi * HDIM + k];
        z0 = fmaf(v, Wc[k * 2 + 0], z0);
        z1 = fmaf(v, Wc[k * 2 + 1], z1);
    }
    float mx = fmaxf(z0, z1);
    float lse = mx + logf(expf(z0 - mx) + expf(z1 - mx));
    out[gi * 2 + 0] = z0 - lse;
    out[gi * 2 + 1] = z1 - lse;
}

// ---------------- launch ----------------------------------------------------
extern "C" void kernel_launch(void* const* d_in, const int* in_sizes, int n_in,
                              void* d_out, int out_size)
{
    const float* x     = (const float*)d_in[0];
    const int* eidx    = (const int*)d_in[1];    // int32
    const int* batch   = (const int*)d_in[2];    // int32
    const float* W1 = (const float*)d_in[3];
    const float* b1 = (const float*)d_in[4];
    const float* W2 = (const float*)d_in[5];
    const float* b2 = (const float*)d_in[6];
    const float* Wc = (const float*)d_in[7];
    const float* bc = (const float*)d_in[8];
    float* out = (float*)d_out;

    const int F = 512;
    int N = in_sizes[0] / F;
    int E = in_sizes[1] / 2;
    const int* src = eidx;
    const int* dst = eidx + E;

    __half* u; __half* h;
    cudaGetSymbolAddress((void**)&u, g_u);
    cudaGetSymbolAddress((void**)&h, g_h);

    int gemm_blocks = (N + 127) / 128;
    int agg_blocks  = (2 * N + 7) / 8;      // 2 warps per row, 8 warps/block
    int pool_warps  = (N + 15) / 16;
    int pool_blocks = (pool_warps * 32 + 255) / 256;
    int scan_blocks = (N + 1023) / 1024;

    // Fork a side stream for the CSR build; GEMM1 (graph-independent)
    // runs concurrently on the capture (default) stream.
    cudaStream_t sb;
    cudaEvent_t evF, evJ;
    cudaStreamCreate(&sb);
    cudaEventCreate(&evF);
    cudaEventCreate(&evJ);

    cudaEventRecord(evF, 0);
    cudaStreamWaitEvent(sb, evF, 0);

    // default stream: GEMM1 (launch 0)
    sgemm_fp16<float><<<gemm_blocks, 256>>>(x, W1, u, N, 512);
    // side stream: coalesced CSR build
    zero_kernel<<<(N + 255) / 256, 256, 0, sb>>>(N);
    hist_kernel<<<(E + 255) / 256, 256, 0, sb>>>(dst, E);
    scan1_kernel<<<scan_blocks, 256, 0, sb>>>(N);     // capture slot (idx 3)
    scan2_kernel<<<1, 128, 0, sb>>>(scan_blocks, N);
    scan3_kernel<<<scan_blocks, 256, 0, sb>>>(N);
    fill_kernel<<<(E + 255) / 256, 256, 0, sb>>>(src, dst, E);
    cudaEventRecord(evJ, sb);
    cudaStreamWaitEvent(0, evJ, 0);                   // join

    agg_kernel<<<agg_blocks, 256>>>(u, h, b1, N);
    sgemm_fp16<__half><<<gemm_blocks, 256>>>(h, W2, u, N, 128);
    agg_kernel<<<agg_blocks, 256>>>(u, h, b2, N);
    pool_kernel<<<pool_blocks, 256>>>(h, batch, N);
    head_kernel<<<1, 64>>>(Wc, bc, out);
}